// round 6
// baseline (speedup 1.0000x reference)
#include <cuda_runtime.h>
#include <cuda_bf16.h>
#include <math.h>
#include <stdint.h>

#define Bv 2
#define Sv 2048
#define Dv 1024
#define Hv 16
#define DKv 64
#define MSZ (Bv * Sv)

// ---------------- scratch ---------------------------------------------------
// bf16 hi/lo splits of raw inputs and weights (GEMM operands)
__device__ __nv_bfloat16 g_qh[MSZ * Dv], g_ql[MSZ * Dv];
__device__ __nv_bfloat16 g_kh[MSZ * Dv], g_kl[MSZ * Dv];
__device__ __nv_bfloat16 g_vh[MSZ * Dv], g_vl[MSZ * Dv];
__device__ __nv_bfloat16 g_wqh[Dv * Dv], g_wql[Dv * Dv];
__device__ __nv_bfloat16 g_wkh[Dv * Dv], g_wkl[Dv * Dv];
__device__ __nv_bfloat16 g_wvh[Dv * Dv], g_wvl[Dv * Dv];
__device__ __nv_bfloat16 g_woh[Dv * Dv], g_wol[Dv * Dv];
// projected Q/K/V in hi/lo bf16 (written by GEMM epilogue)
__device__ __nv_bfloat16 g_Qh[MSZ * Dv], g_Ql[MSZ * Dv];
__device__ __nv_bfloat16 g_Kh[MSZ * Dv], g_Kl[MSZ * Dv];
__device__ __nv_bfloat16 g_Vh[MSZ * Dv], g_Vl[MSZ * Dv];
// attention context hi/lo
__device__ __nv_bfloat16 g_ch[MSZ * Dv], g_cl[MSZ * Dv];

// ---------------- helpers ----------------------------------------------------
__device__ __forceinline__ uint32_t smem_u32(const void* p) {
    uint32_t a;
    asm("{ .reg .u64 t; cvta.to.shared.u64 t, %1; cvt.u32.u64 %0, t; }" : "=r"(a) : "l"(p));
    return a;
}
__device__ __forceinline__ void split4(float4 v, uint2& h, uint2& l) {
    __nv_bfloat162 h01 = __float22bfloat162_rn(make_float2(v.x, v.y));
    __nv_bfloat162 h23 = __float22bfloat162_rn(make_float2(v.z, v.w));
    float2 f01 = __bfloat1622float2(h01);
    float2 f23 = __bfloat1622float2(h23);
    __nv_bfloat162 l01 = __float22bfloat162_rn(make_float2(v.x - f01.x, v.y - f01.y));
    __nv_bfloat162 l23 = __float22bfloat162_rn(make_float2(v.z - f23.x, v.w - f23.y));
    h.x = *(uint32_t*)&h01; h.y = *(uint32_t*)&h23;
    l.x = *(uint32_t*)&l01; l.y = *(uint32_t*)&l23;
}
__device__ __forceinline__ void split2(float a, float b, uint32_t& h, uint32_t& l) {
    __nv_bfloat162 hb = __float22bfloat162_rn(make_float2(a, b));
    float2 hf = __bfloat1622float2(hb);
    __nv_bfloat162 lb = __float22bfloat162_rn(make_float2(a - hf.x, b - hf.y));
    h = *(uint32_t*)&hb; l = *(uint32_t*)&lb;
}
__device__ __forceinline__ void mma_bf16(float* d, const uint32_t* a, const uint32_t* b) {
    asm volatile(
        "mma.sync.aligned.m16n8k16.row.col.f32.bf16.bf16.f32 "
        "{%0,%1,%2,%3}, {%4,%5,%6,%7}, {%8,%9}, {%0,%1,%2,%3};"
        : "+f"(d[0]), "+f"(d[1]), "+f"(d[2]), "+f"(d[3])
        : "r"(a[0]), "r"(a[1]), "r"(a[2]), "r"(a[3]), "r"(b[0]), "r"(b[1]));
}
__device__ __forceinline__ void ldsm_x2_t(uint32_t& r0, uint32_t& r1, uint32_t addr) {
    asm volatile("ldmatrix.sync.aligned.m8n8.x2.trans.shared.b16 {%0,%1}, [%2];"
                 : "=r"(r0), "=r"(r1) : "r"(addr));
}
__device__ __forceinline__ void cp16(uint32_t s, const void* g) {
    asm volatile("cp.async.cg.shared.global [%0], [%1], 16;" :: "r"(s), "l"(g));
}
#define CP_COMMIT() asm volatile("cp.async.commit_group;" ::: "memory")
#define CP_WAIT1()  asm volatile("cp.async.wait_group 1;" ::: "memory")
#define CP_WAIT2()  asm volatile("cp.async.wait_group 2;" ::: "memory")

// ---------------- split kernel ------------------------------------------------
__global__ void split_kernel(const float4* __restrict__ src, uint2* __restrict__ hi,
                             uint2* __restrict__ lo, int n4) {
    int i = blockIdx.x * blockDim.x + threadIdx.x;
    if (i < n4) {
        uint2 h, l;
        split4(src[i], h, l);
        hi[i] = h; lo[i] = l;
    }
}

// ---------------- GEMM: C = A * B^T, bf16 hi/lo in, fp32 OR bf16-split out ----
#define KC 32
#define NCH (Dv / KC)           // 32
#define ROWB 80
#define TILEB (128 * ROWB)      // 10240
#define STAGEB (4 * TILEB)      // 40960
#define GEMM_SMEM (4 * STAGEB)  // 163840

__global__ __launch_bounds__(256, 1)
void gemm_tc(const __nv_bfloat16* __restrict__ Ah, const __nv_bfloat16* __restrict__ Al,
             const __nv_bfloat16* __restrict__ Bh, const __nv_bfloat16* __restrict__ Bl,
             float* __restrict__ C,
             __nv_bfloat16* __restrict__ Ch, __nv_bfloat16* __restrict__ Cl) {
    extern __shared__ char smem[];
    const uint32_t sbase = smem_u32(smem);
    const int tid = threadIdx.x;
    const int wid = tid >> 5;
    const int lid = tid & 31;
    const int g = lid >> 2;
    const int tig = lid & 3;
    const int warp_m = wid & 1;
    const int warp_n = wid >> 1;
    const int row0 = blockIdx.y * 128;
    const int col0 = blockIdx.x * 128;

    const __nv_bfloat16* srcs[4] = {Ah, Al, Bh, Bl};
    const int mytile = wid >> 1;
    const int myhalf = wid & 1;
    const __nv_bfloat16* mysrc = srcs[mytile];
    const int myrbase = (mytile < 2) ? row0 : col0;

    float acc[4][4][4];
#pragma unroll
    for (int i = 0; i < 4; ++i)
#pragma unroll
        for (int j = 0; j < 4; ++j)
#pragma unroll
            for (int e = 0; e < 4; ++e) acc[i][j][e] = 0.f;

    auto issue = [&](int chunk, int st) {
        const int k0 = chunk * KC;
#pragma unroll
        for (int rr = 0; rr < 2; ++rr) {
            int r = myhalf * 64 + rr * 32 + lid;
            const char* gp = (const char*)(mysrc + (size_t)(myrbase + r) * Dv + k0);
            uint32_t sa = sbase + st * STAGEB + mytile * TILEB + r * ROWB;
#pragma unroll
            for (int q = 0; q < 4; ++q) cp16(sa + q * 16, gp + q * 16);
        }
    };

    auto compute = [&](int s) {
        const char* st = smem + s * STAGEB;
#pragma unroll
        for (int ks = 0; ks < 2; ++ks) {
            const int kb = ks * 32;
            uint32_t ah[4][4], al[4][4], bh[4][2], bl[4][2];
#pragma unroll
            for (int mt = 0; mt < 4; ++mt) {
                int r = warp_m * 64 + mt * 16 + g;
                const char* p = st + r * ROWB + tig * 4 + kb;
                ah[mt][0] = *(const uint32_t*)(p);
                ah[mt][1] = *(const uint32_t*)(p + 8 * ROWB);
                ah[mt][2] = *(const uint32_t*)(p + 16);
                ah[mt][3] = *(const uint32_t*)(p + 8 * ROWB + 16);
                al[mt][0] = *(const uint32_t*)(p + TILEB);
                al[mt][1] = *(const uint32_t*)(p + TILEB + 8 * ROWB);
                al[mt][2] = *(const uint32_t*)(p + TILEB + 16);
                al[mt][3] = *(const uint32_t*)(p + TILEB + 8 * ROWB + 16);
            }
#pragma unroll
            for (int nt = 0; nt < 4; ++nt) {
                int r = warp_n * 32 + nt * 8 + g;
                const char* p = st + 2 * TILEB + r * ROWB + tig * 4 + kb;
                bh[nt][0] = *(const uint32_t*)(p);
                bh[nt][1] = *(const uint32_t*)(p + 16);
                bl[nt][0] = *(const uint32_t*)(p + TILEB);
                bl[nt][1] = *(const uint32_t*)(p + TILEB + 16);
            }
#pragma unroll
            for (int mt = 0; mt < 4; ++mt)
#pragma unroll
                for (int nt = 0; nt < 4; ++nt) {
                    mma_bf16(acc[mt][nt], ah[mt], bh[nt]);
                    mma_bf16(acc[mt][nt], ah[mt], bl[nt]);
                    mma_bf16(acc[mt][nt], al[mt], bh[nt]);
                }
        }
    };

#pragma unroll
    for (int p = 0; p < 3; ++p) {
        issue(p, p);
        CP_COMMIT();
    }
    for (int i = 0; i < NCH; ++i) {
        CP_WAIT2();
        __syncthreads();
        if (i + 3 < NCH) issue(i + 3, (i + 3) & 3);
        CP_COMMIT();
        compute(i & 3);
    }

#pragma unroll
    for (int mt = 0; mt < 4; ++mt)
#pragma unroll
        for (int nt = 0; nt < 4; ++nt) {
            int r = row0 + warp_m * 64 + mt * 16 + g;
            int c = col0 + warp_n * 32 + nt * 8 + 2 * tig;
            float* d = acc[mt][nt];
            if (Cl) {
                uint32_t h01, l01, h23, l23;
                split2(d[0], d[1], h01, l01);
                split2(d[2], d[3], h23, l23);
                *(uint32_t*)&Ch[(size_t)r * Dv + c] = h01;
                *(uint32_t*)&Cl[(size_t)r * Dv + c] = l01;
                *(uint32_t*)&Ch[(size_t)(r + 8) * Dv + c] = h23;
                *(uint32_t*)&Cl[(size_t)(r + 8) * Dv + c] = l23;
            } else {
                *(float2*)&C[(size_t)r * Dv + c] = make_float2(d[0], d[1]);
                *(float2*)&C[(size_t)(r + 8) * Dv + c] = make_float2(d[2], d[3]);
            }
        }
}

// ---------------- tensor-core flash attention ---------------------------------
// CTA: 128 queries of one (b,h), 8 warps x 16 rows. K/V tiles of 64, pre-split
// bf16 hi/lo staged via double-buffered cp.async. 3x-split QK^T and P.V.
#define FP 144
#define FQB (128 * FP)            // 18432 (one Q tile)
#define FKB (64 * FP)             // 9216  (one K/V tile)
#define FSTAGE (4 * FKB)          // 36864: kh, kl, vh, vl
#define FLASH_SMEM (2 * FQB + 2 * FSTAGE)   // 110592

__global__ __launch_bounds__(256, 2)
void flash_mma(const __nv_bfloat16* __restrict__ Qh, const __nv_bfloat16* __restrict__ Ql,
               const __nv_bfloat16* __restrict__ Kh, const __nv_bfloat16* __restrict__ Kl,
               const __nv_bfloat16* __restrict__ Vh, const __nv_bfloat16* __restrict__ Vl,
               __nv_bfloat16* __restrict__ Ch, __nv_bfloat16* __restrict__ Cl) {
    extern __shared__ char fsm[];
    const uint32_t sbase = smem_u32(fsm);
    char* sQh = fsm;
    char* sQl = fsm + FQB;

    const int bh = blockIdx.y;
    const int b = bh >> 4;
    const int h = bh & 15;
    const int qt = (int)gridDim.x - 1 - (int)blockIdx.x;   // heavy CTAs first
    const int q0 = qt * 128;
    const int tid = threadIdx.x;
    const int w = tid >> 5;
    const int lane = tid & 31;
    const int g = lane >> 2;
    const int tig = lane & 3;
    const int ntiles = qt * 2 + 2;

    // ---- stage Q hi/lo (one row of one tile per thread) ----
    {
        const int tile = tid >> 7;            // 0: hi, 1: lo
        const int r = tid & 127;
        const __nv_bfloat16* src = (tile == 0 ? Qh : Ql) + (size_t)(b * Sv + q0 + r) * Dv + h * DKv;
        uint32_t dst = sbase + tile * FQB + r * FP;
#pragma unroll
        for (int q = 0; q < 8; ++q) cp16(dst + q * 16, (const char*)src + q * 16);
    }

    auto issueKV = [&](int kt, int st) {
        const int k0 = kt * 64;
        const int tile = tid >> 6;            // 0:kh 1:kl 2:vh 3:vl
        const int r = tid & 63;
        const __nv_bfloat16* bases[4] = {Kh, Kl, Vh, Vl};
        const __nv_bfloat16* src = bases[tile] + (size_t)(b * Sv + k0 + r) * Dv + h * DKv;
        uint32_t dst = sbase + 2 * FQB + st * FSTAGE + tile * FKB + r * FP;
#pragma unroll
        for (int q = 0; q < 8; ++q) cp16(dst + q * 16, (const char*)src + q * 16);
    };

    issueKV(0, 0);
    CP_COMMIT();
    issueKV(1, 1);
    CP_COMMIT();

    float oacc[8][4];
#pragma unroll
    for (int nt = 0; nt < 8; ++nt)
#pragma unroll
        for (int e = 0; e < 4; ++e) oacc[nt][e] = 0.f;
    float m0 = -1e30f, m1 = -1e30f, l0 = 0.f, l1 = 0.f;

    for (int kt = 0; kt < ntiles; ++kt) {
        const int st = kt & 1;
        const int k0 = kt * 64;
        const char* sKh = fsm + 2 * FQB + st * FSTAGE;
        const char* sKl = sKh + FKB;
        const uint32_t sVh_u = sbase + 2 * FQB + st * FSTAGE + 2 * FKB;
        const uint32_t sVl_u = sVh_u + FKB;

        CP_WAIT1();              // stage kt (and Q on kt=0) complete
        __syncthreads();

        // ---- S = Q K^T (3x split) ----
        float s[8][4];
#pragma unroll
        for (int nt = 0; nt < 8; ++nt)
#pragma unroll
            for (int e = 0; e < 4; ++e) s[nt][e] = 0.f;
#pragma unroll
        for (int ks = 0; ks < 4; ++ks) {
            const int kb = ks * 32;
            uint32_t ah[4], al[4];
            const char* pq = sQh + (w * 16 + g) * FP + tig * 4 + kb;
            ah[0] = *(const uint32_t*)(pq);
            ah[1] = *(const uint32_t*)(pq + 8 * FP);
            ah[2] = *(const uint32_t*)(pq + 16);
            ah[3] = *(const uint32_t*)(pq + 8 * FP + 16);
            const char* pl = sQl + (w * 16 + g) * FP + tig * 4 + kb;
            al[0] = *(const uint32_t*)(pl);
            al[1] = *(const uint32_t*)(pl + 8 * FP);
            al[2] = *(const uint32_t*)(pl + 16);
            al[3] = *(const uint32_t*)(pl + 8 * FP + 16);
#pragma unroll
            for (int nt = 0; nt < 8; ++nt) {
                uint32_t bh2[2], bl2[2];
                const char* pk = sKh + (nt * 8 + g) * FP + tig * 4 + kb;
                bh2[0] = *(const uint32_t*)(pk);
                bh2[1] = *(const uint32_t*)(pk + 16);
                const char* pk2 = sKl + (nt * 8 + g) * FP + tig * 4 + kb;
                bl2[0] = *(const uint32_t*)(pk2);
                bl2[1] = *(const uint32_t*)(pk2 + 16);
                mma_bf16(s[nt], ah, bh2);
                mma_bf16(s[nt], ah, bl2);
                mma_bf16(s[nt], al, bh2);
            }
        }

        // ---- scale + causal mask ----
        const bool domask = (k0 + 64 > q0);
        const int rlo = q0 + w * 16 + g;
        const int rhi = rlo + 8;
#pragma unroll
        for (int nt = 0; nt < 8; ++nt) {
            s[nt][0] *= 0.125f; s[nt][1] *= 0.125f;
            s[nt][2] *= 0.125f; s[nt][3] *= 0.125f;
            if (domask) {
                int c0 = k0 + nt * 8 + 2 * tig;
                if (c0 > rlo) s[nt][0] = -1e30f;
                if (c0 + 1 > rlo) s[nt][1] = -1e30f;
                if (c0 > rhi) s[nt][2] = -1e30f;
                if (c0 + 1 > rhi) s[nt][3] = -1e30f;
            }
        }

        // ---- online softmax ----
        float mx0 = -1e30f, mx1 = -1e30f;
#pragma unroll
        for (int nt = 0; nt < 8; ++nt) {
            mx0 = fmaxf(mx0, fmaxf(s[nt][0], s[nt][1]));
            mx1 = fmaxf(mx1, fmaxf(s[nt][2], s[nt][3]));
        }
        mx0 = fmaxf(mx0, __shfl_xor_sync(0xffffffffu, mx0, 1));
        mx0 = fmaxf(mx0, __shfl_xor_sync(0xffffffffu, mx0, 2));
        mx1 = fmaxf(mx1, __shfl_xor_sync(0xffffffffu, mx1, 1));
        mx1 = fmaxf(mx1, __shfl_xor_sync(0xffffffffu, mx1, 2));
        float mn0 = fmaxf(m0, mx0), mn1 = fmaxf(m1, mx1);
        float a0 = __expf(m0 - mn0), a1 = __expf(m1 - mn1);
        m0 = mn0; m1 = mn1;

        float ps0 = 0.f, ps1 = 0.f;
#pragma unroll
        for (int nt = 0; nt < 8; ++nt) {
            s[nt][0] = __expf(s[nt][0] - m0);
            s[nt][1] = __expf(s[nt][1] - m0);
            s[nt][2] = __expf(s[nt][2] - m1);
            s[nt][3] = __expf(s[nt][3] - m1);
            ps0 += s[nt][0] + s[nt][1];
            ps1 += s[nt][2] + s[nt][3];
        }
        ps0 += __shfl_xor_sync(0xffffffffu, ps0, 1);
        ps0 += __shfl_xor_sync(0xffffffffu, ps0, 2);
        ps1 += __shfl_xor_sync(0xffffffffu, ps1, 1);
        ps1 += __shfl_xor_sync(0xffffffffu, ps1, 2);
        l0 = l0 * a0 + ps0;
        l1 = l1 * a1 + ps1;
#pragma unroll
        for (int nt = 0; nt < 8; ++nt) {
            oacc[nt][0] *= a0; oacc[nt][1] *= a0;
            oacc[nt][2] *= a1; oacc[nt][3] *= a1;
        }

        // ---- O += P V (3x split) ----
#pragma unroll
        for (int kc = 0; kc < 4; ++kc) {
            uint32_t pah[4], pal[4];
            split2(s[2 * kc][0], s[2 * kc][1], pah[0], pal[0]);
            split2(s[2 * kc][2], s[2 * kc][3], pah[1], pal[1]);
            split2(s[2 * kc + 1][0], s[2 * kc + 1][1], pah[2], pal[2]);
            split2(s[2 * kc + 1][2], s[2 * kc + 1][3], pah[3], pal[3]);
            uint32_t rowoff = (uint32_t)((kc * 16 + (lane & 15)) * FP);
#pragma unroll
            for (int nt = 0; nt < 8; ++nt) {
                uint32_t vh2[2], vl2[2];
                ldsm_x2_t(vh2[0], vh2[1], sVh_u + rowoff + nt * 16);
                ldsm_x2_t(vl2[0], vl2[1], sVl_u + rowoff + nt * 16);
                mma_bf16(oacc[nt], pah, vh2);
                mma_bf16(oacc[nt], pah, vl2);
                mma_bf16(oacc[nt], pal, vh2);
            }
        }

        __syncthreads();                    // stage kt free for reuse
        if (kt + 2 < ntiles) issueKV(kt + 2, st);
        CP_COMMIT();                        // uniform group accounting
    }

    // ---- epilogue ----
    float inv0 = 1.f / l0, inv1 = 1.f / l1;
    const size_t rlo = (size_t)(b * Sv + q0 + w * 16 + g);
    const size_t rhi = rlo + 8;
#pragma unroll
    for (int nt = 0; nt < 8; ++nt) {
        int c = h * DKv + nt * 8 + 2 * tig;
        float f0 = oacc[nt][0] * inv0, f1 = oacc[nt][1] * inv0;
        float f2 = oacc[nt][2] * inv1, f3 = oacc[nt][3] * inv1;
        uint32_t h01, l01, h23, l23;
        split2(f0, f1, h01, l01);
        split2(f2, f3, h23, l23);
        *(uint32_t*)&Ch[rlo * Dv + c] = h01;
        *(uint32_t*)&Cl[rlo * Dv + c] = l01;
        *(uint32_t*)&Ch[rhi * Dv + c] = h23;
        *(uint32_t*)&Cl[rhi * Dv + c] = l23;
    }
}

// ---------------- launch --------------------------------------------------------
extern "C" void kernel_launch(void* const* d_in, const int* in_sizes, int n_in,
                              void* d_out, int out_size) {
    const float* q  = (const float*)d_in[0];
    const float* k  = (const float*)d_in[1];
    const float* v  = (const float*)d_in[2];
    // d_in[3] = mask (tril) — handled analytically
    const float* Wq = (const float*)d_in[4];
    const float* Wk = (const float*)d_in[5];
    const float* Wv = (const float*)d_in[6];
    const float* Wo = (const float*)d_in[7];
    float* out = (float*)d_out;

    __nv_bfloat16 *qh, *ql, *kh, *kl, *vh, *vl;
    __nv_bfloat16 *wqh, *wql, *wkh, *wkl, *wvh, *wvl, *woh, *wol;
    __nv_bfloat16 *Qh, *Ql, *Kh, *Kl, *Vh, *Vl, *ch, *cl;
    cudaGetSymbolAddress((void**)&qh, g_qh);  cudaGetSymbolAddress((void**)&ql, g_ql);
    cudaGetSymbolAddress((void**)&kh, g_kh);  cudaGetSymbolAddress((void**)&kl, g_kl);
    cudaGetSymbolAddress((void**)&vh, g_vh);  cudaGetSymbolAddress((void**)&vl, g_vl);
    cudaGetSymbolAddress((void**)&wqh, g_wqh); cudaGetSymbolAddress((void**)&wql, g_wql);
    cudaGetSymbolAddress((void**)&wkh, g_wkh); cudaGetSymbolAddress((void**)&wkl, g_wkl);
    cudaGetSymbolAddress((void**)&wvh, g_wvh); cudaGetSymbolAddress((void**)&wvl, g_wvl);
    cudaGetSymbolAddress((void**)&woh, g_woh); cudaGetSymbolAddress((void**)&wol, g_wol);
    cudaGetSymbolAddress((void**)&Qh, g_Qh);  cudaGetSymbolAddress((void**)&Ql, g_Ql);
    cudaGetSymbolAddress((void**)&Kh, g_Kh);  cudaGetSymbolAddress((void**)&Kl, g_Kl);
    cudaGetSymbolAddress((void**)&Vh, g_Vh);  cudaGetSymbolAddress((void**)&Vl, g_Vl);
    cudaGetSymbolAddress((void**)&ch, g_ch);  cudaGetSymbolAddress((void**)&cl, g_cl);

    const int nQK4 = MSZ * Dv / 4;
    const int nW4  = Dv * Dv / 4;
    split_kernel<<<nQK4 / 256, 256>>>((const float4*)q, (uint2*)qh, (uint2*)ql, nQK4);
    split_kernel<<<nQK4 / 256, 256>>>((const float4*)k, (uint2*)kh, (uint2*)kl, nQK4);
    split_kernel<<<nQK4 / 256, 256>>>((const float4*)v, (uint2*)vh, (uint2*)vl, nQK4);
    split_kernel<<<nW4 / 256, 256>>>((const float4*)Wq, (uint2*)wqh, (uint2*)wql, nW4);
    split_kernel<<<nW4 / 256, 256>>>((const float4*)Wk, (uint2*)wkh, (uint2*)wkl, nW4);
    split_kernel<<<nW4 / 256, 256>>>((const float4*)Wv, (uint2*)wvh, (uint2*)wvl, nW4);
    split_kernel<<<nW4 / 256, 256>>>((const float4*)Wo, (uint2*)woh, (uint2*)wol, nW4);

    cudaFuncSetAttribute(gemm_tc, cudaFuncAttributeMaxDynamicSharedMemorySize, GEMM_SMEM);
    cudaFuncSetAttribute(flash_mma, cudaFuncAttributeMaxDynamicSharedMemorySize, FLASH_SMEM);

    dim3 gblock(256);
    dim3 ggrid(Dv / 128, MSZ / 128);   // (8, 32)
    gemm_tc<<<ggrid, gblock, GEMM_SMEM>>>(qh, ql, wqh, wql, nullptr, Qh, Ql);
    gemm_tc<<<ggrid, gblock, GEMM_SMEM>>>(kh, kl, wkh, wkl, nullptr, Kh, Kl);
    gemm_tc<<<ggrid, gblock, GEMM_SMEM>>>(vh, vl, wvh, wvl, nullptr, Vh, Vl);

    dim3 agrid(Sv / 128, Bv * Hv);     // (16, 32)
    flash_mma<<<agrid, 256, FLASH_SMEM>>>(Qh, Ql, Kh, Kl, Vh, Vl, ch, cl);

    gemm_tc<<<ggrid, gblock, GEMM_SMEM>>>(ch, cl, woh, wol, out, nullptr, nullptr);
}